// round 1
// baseline (speedup 1.0000x reference)
#include <cuda_runtime.h>
#include <stdint.h>

#define N_NODES 16384
#define BATCH   2
#define FEAT    32
#define GRU     16
#define OUTD    16
#define COLS    32          // BATCH * OUTD fused columns
#define CATD    48          // FEAT + GRU

// Scratch: Y = cat @ W, layout [n][c] with c = b*16 + o  (2 MB, L2-resident)
__device__ float g_Y[N_NODES * COLS];

// ---------------------------------------------------------------------------
// Kernel A: Y[n, b*16+o] = sum_f inputs[b,n,f]*W[f,o] + sum_g h[b,n,g]*W[F+g,o]
// Tiny (50 MFLOP). One thread per (n, c).
// ---------------------------------------------------------------------------
__global__ void __launch_bounds__(256) compute_y_kernel(
    const float* __restrict__ inputs,
    const float* __restrict__ hidden,
    const float* __restrict__ W)
{
    __shared__ float sW[CATD * OUTD];
    for (int i = threadIdx.x; i < CATD * OUTD; i += blockDim.x)
        sW[i] = W[i];
    __syncthreads();

    int t = blockIdx.x * blockDim.x + threadIdx.x;
    if (t >= N_NODES * COLS) return;
    int n = t >> 5;
    int c = t & 31;
    int b = c >> 4;
    int o = c & 15;

    const float* in_row = inputs + ((size_t)b * N_NODES + n) * FEAT;
    const float* h_row  = hidden + ((size_t)b * N_NODES + n) * GRU;

    float acc = 0.f;
#pragma unroll
    for (int f = 0; f < FEAT; f++)
        acc = fmaf(in_row[f], sW[f * OUTD + o], acc);
#pragma unroll
    for (int g = 0; g < GRU; g++)
        acc = fmaf(h_row[g], sW[(FEAT + g) * OUTD + o], acc);

    g_Y[t] = acc;
}

// ---------------------------------------------------------------------------
// Kernel B: out[b, m*16+o] = sum_n L[m,n] * Y[n, c] + bias[o]
// One warp per row m. Stream the 64 KB row as uint4 with a depth-4 prefetch
// ring; ballot nonzero lanes; shfl-broadcast nnz; each lane FMAs its column.
// Zeros in L are exact +0.0 (adjacency is {0,1}) so an integer test is safe.
// ---------------------------------------------------------------------------
__global__ void __launch_bounds__(256) spmm_kernel(
    const float* __restrict__ L,
    const float* __restrict__ bias,
    float* __restrict__ out)
{
    const int warp = (blockIdx.x * blockDim.x + threadIdx.x) >> 5;
    const int lane = threadIdx.x & 31;
    if (warp >= N_NODES) return;

    const uint4* __restrict__ row =
        reinterpret_cast<const uint4*>(L + (size_t)warp * N_NODES);
    const float* __restrict__ Y = g_Y;

    const int NITER = N_NODES / 128;   // 128 iterations, 128 floats/warp each

    float acc = 0.f;
    uint4 buf[4];
#pragma unroll
    for (int j = 0; j < 4; j++)
        buf[j] = row[j * 32 + lane];

#pragma unroll 4
    for (int it = 0; it < NITER; it++) {
        uint4 v = buf[it & 3];
        int pf = it + 4;
        if (pf < NITER)                       // uniform predicate
            buf[it & 3] = row[pf * 32 + lane];

        unsigned any  = (v.x | v.y | v.z | v.w);
        unsigned mask = __ballot_sync(0xffffffffu, any != 0u);

        while (mask) {
            int src = __ffs(mask) - 1;
            mask &= mask - 1;
            unsigned w0 = __shfl_sync(0xffffffffu, v.x, src);
            unsigned w1 = __shfl_sync(0xffffffffu, v.y, src);
            unsigned w2 = __shfl_sync(0xffffffffu, v.z, src);
            unsigned w3 = __shfl_sync(0xffffffffu, v.w, src);
            int nbase = (it * 32 + src) * 4;
            if (w0) acc = fmaf(__uint_as_float(w0), Y[(nbase + 0) * 32 + lane], acc);
            if (w1) acc = fmaf(__uint_as_float(w1), Y[(nbase + 1) * 32 + lane], acc);
            if (w2) acc = fmaf(__uint_as_float(w2), Y[(nbase + 2) * 32 + lane], acc);
            if (w3) acc = fmaf(__uint_as_float(w3), Y[(nbase + 3) * 32 + lane], acc);
        }
    }

    const int b = lane >> 4;
    const int o = lane & 15;
    acc += bias[o];
    out[(size_t)b * (N_NODES * OUTD) + (size_t)warp * OUTD + o] = acc;
}

// ---------------------------------------------------------------------------
// Launch
// ---------------------------------------------------------------------------
extern "C" void kernel_launch(void* const* d_in, const int* in_sizes, int n_in,
                              void* d_out, int out_size)
{
    const float* inputs  = (const float*)d_in[0];  // [2, 16384, 32]
    const float* hidden  = (const float*)d_in[1];  // [2, 16384*16]
    const float* lap     = (const float*)d_in[2];  // [16384, 16384]
    const float* weights = (const float*)d_in[3];  // [48, 16]
    const float* biases  = (const float*)d_in[4];  // [16]
    float* out = (float*)d_out;                    // [2, 16384*16]

    (void)in_sizes; (void)n_in; (void)out_size;

    // Kernel A: 16384*32 threads
    {
        int total = N_NODES * COLS;
        int block = 256;
        int grid  = (total + block - 1) / block;
        compute_y_kernel<<<grid, block>>>(inputs, hidden, weights);
    }

    // Kernel B: one warp per row -> 16384 warps, 8 warps/block
    {
        int block = 256;
        int grid  = (N_NODES * 32 + block - 1) / block;
        spmm_kernel<<<grid, block>>>(lap, biases, out);
    }
}